// round 5
// baseline (speedup 1.0000x reference)
#include <cuda_runtime.h>
#include <math.h>

// Problem shape (fixed): x [T=4, B=32, C=256, H=32, W=32]
#define Tn 4
#define Bn 32
#define Cn 256
#define Pn 1024
#define NSL 1024            // slices = B * 32 chunks (8 channels each)
#define NBLK 148            // persistent grid = one CTA per SM

// partial4[sel][slice][pg] : sel 0 = csum, 1 = ssq. 2*1024*256 float4 = 8 MB (L2-resident)
__device__ float4 g_partial4[2 * NSL * 256];
// combined per-pixel: [sel][b][p], 2*32*1024 floats = 256 KB
__device__ float g_comb[2 * Bn * Pn];

__device__ __forceinline__ float4 f4add(float4 a, float4 b) {
    return make_float4(a.x + b.x, a.y + b.y, a.z + b.z, a.w + b.w);
}
__device__ __forceinline__ float4 f4fma(float4 a, float4 b, float4 c) {
    return make_float4(fmaf(a.x, b.x, c.x), fmaf(a.y, b.y, c.y),
                       fmaf(a.z, b.z, c.z), fmaf(a.w, b.w, c.w));
}

// ---------------------------------------------------------------------------
// Persistent reduce: slice = (b, chunk of 8 channels). 1024 threads:
//   pg = tid&255 (4 pixels via float4), csub = tid>>8 (2 channels).
// Software pipeline: next slice's 8 LDG.128 issued before the barrier phase.
// ---------------------------------------------------------------------------
__global__ void __launch_bounds__(1024, 1) reduce_kernel(const float* __restrict__ xf) {
    const float4* __restrict__ X = (const float4*)xf;
    const int tid  = threadIdx.x;
    const int pg   = tid & 255;
    const int csub = tid >> 8;

    __shared__ float4 scs[3][256];
    __shared__ float4 ssq[3][256];

    const size_t tstr = (size_t)Bn * Cn * 256;   // t-plane stride in float4

    int sl = blockIdx.x;
    float4 r[8];
    {
        const int b = sl >> 5, ch = sl & 31;
        const int c = ch * 8 + csub * 2;
        const size_t base = ((size_t)b * Cn + c) * 256 + pg;
#pragma unroll
        for (int t = 0; t < 4; ++t) {
            r[t]     = __ldg(X + base + (size_t)t * tstr);
            r[4 + t] = __ldg(X + base + 256 + (size_t)t * tstr);
        }
    }

    for (;;) {
        float4 m0, m1;
        m0.x = (r[0].x + r[1].x + r[2].x + r[3].x) * 0.25f;
        m0.y = (r[0].y + r[1].y + r[2].y + r[3].y) * 0.25f;
        m0.z = (r[0].z + r[1].z + r[2].z + r[3].z) * 0.25f;
        m0.w = (r[0].w + r[1].w + r[2].w + r[3].w) * 0.25f;
        m1.x = (r[4].x + r[5].x + r[6].x + r[7].x) * 0.25f;
        m1.y = (r[4].y + r[5].y + r[6].y + r[7].y) * 0.25f;
        m1.z = (r[4].z + r[5].z + r[6].z + r[7].z) * 0.25f;
        m1.w = (r[4].w + r[5].w + r[6].w + r[7].w) * 0.25f;

        float4 cs4 = f4add(m0, m1);
        float4 sq4 = f4fma(m1, m1, f4fma(m0, m0, make_float4(0.f, 0.f, 0.f, 0.f)));

        const int cur  = sl;
        const int nxt  = sl + NBLK;
        const bool more = (nxt < NSL);

        if (more) {   // issue next slice's loads NOW; they fly across the barriers
            const int b = nxt >> 5, ch = nxt & 31;
            const int c = ch * 8 + csub * 2;
            const size_t base = ((size_t)b * Cn + c) * 256 + pg;
#pragma unroll
            for (int t = 0; t < 4; ++t) {
                r[t]     = __ldg(X + base + (size_t)t * tstr);
                r[4 + t] = __ldg(X + base + 256 + (size_t)t * tstr);
            }
        }

        if (csub) { scs[csub - 1][pg] = cs4; ssq[csub - 1][pg] = sq4; }
        __syncthreads();
        if (!csub) {
            cs4 = f4add(f4add(cs4, scs[0][pg]), f4add(scs[1][pg], scs[2][pg]));
            sq4 = f4add(f4add(sq4, ssq[0][pg]), f4add(ssq[1][pg], ssq[2][pg]));
            g_partial4[(size_t)cur * 256 + pg] = cs4;
            g_partial4[(size_t)(NSL + cur) * 256 + pg] = sq4;
        }
        if (!more) break;
        __syncthreads();
        sl = nxt;
    }
}

// ---------------------------------------------------------------------------
// Combine: 65536 threads, one output each. out[sel][b][p] = sum over 32
// chunk-slices of partial[sel][b*32+ch][p]. All traffic L2-resident.
// ---------------------------------------------------------------------------
__global__ void __launch_bounds__(256) combine_kernel() {
    const float* __restrict__ P = (const float*)g_partial4;
    const int idx = blockIdx.x * 256 + threadIdx.x;    // 0..65535
    const int sel = idx >> 15;                         // 0 = cs, 1 = sq
    const int b   = (idx >> 10) & 31;
    const int p   = idx & 1023;

    const size_t base = ((size_t)sel * NSL + (size_t)b * 32) * 1024 + p;
    float acc = 0.f;
#pragma unroll
    for (int ch = 0; ch < 32; ++ch)
        acc += __ldg(P + base + (size_t)ch * 1024);

    g_comb[idx] = acc;
}

// ---------------------------------------------------------------------------
// Final: per batch — per-pixel cs/sq (256 KB in L2), 3x3 zero-padded box
// filter, cosine collapse, mask, softmax over 1024 pixels.
// ---------------------------------------------------------------------------
__global__ void __launch_bounds__(1024) final_kernel(const int* __restrict__ mask,
                                                     float* __restrict__ out) {
    const int b    = blockIdx.x;
    const int tid  = threadIdx.x;           // pixel index
    const int h    = tid >> 5;
    const int w    = tid & 31;
    const int lane = tid & 31;
    const int wid  = tid >> 5;

    const float cs = __ldg(&g_comb[(size_t)b * Pn + tid]);
    const float sq = __ldg(&g_comb[(size_t)(Bn + b) * Pn + tid]);
    const int mraw = __ldg(&mask[(size_t)b * Pn + tid]);

    // 3x3 zero-padded box sum over 32x32
    __shared__ float s_cs[34 * 34];
    for (int i = tid; i < 34 * 34; i += 1024) s_cs[i] = 0.f;
    __syncthreads();
    s_cs[(h + 1) * 34 + (w + 1)] = cs;
    __syncthreads();

    float box = 0.f;
#pragma unroll
    for (int dh = 0; dh < 3; ++dh)
#pragma unroll
        for (int dw = 0; dw < 3; ++dw)
            box += s_cs[(h + dh) * 34 + (w + dw)];

    const float lm  = box * (1.f / 9.f);
    const float nx  = sqrtf(sq);
    const float ny  = 16.f * fabsf(lm);       // sqrt(C)=16
    const float sim = (lm * cs) / (fmaxf(nx, 1e-6f) * fmaxf(ny, 1e-6f));
    const float score = mraw ? -INFINITY : -sim;

    // block softmax over 1024 entries
    __shared__ float red[32];
    __shared__ float bc[2];

    float m = score;
#pragma unroll
    for (int o = 16; o; o >>= 1) m = fmaxf(m, __shfl_xor_sync(0xFFFFFFFFu, m, o));
    if (lane == 0) red[wid] = m;
    __syncthreads();
    if (wid == 0) {
        float v = red[lane];
#pragma unroll
        for (int o = 16; o; o >>= 1) v = fmaxf(v, __shfl_xor_sync(0xFFFFFFFFu, v, o));
        if (lane == 0) bc[0] = v;
    }
    __syncthreads();
    const float gmax = bc[0];

    const float e = __expf(score - gmax);
    float s = e;
#pragma unroll
    for (int o = 16; o; o >>= 1) s += __shfl_xor_sync(0xFFFFFFFFu, s, o);
    if (lane == 0) red[wid] = s;
    __syncthreads();
    if (wid == 0) {
        float v = red[lane];
#pragma unroll
        for (int o = 16; o; o >>= 1) v += __shfl_xor_sync(0xFFFFFFFFu, v, o);
        if (lane == 0) bc[1] = v;
    }
    __syncthreads();

    out[(size_t)b * Pn + tid] = e * __frcp_rn(bc[1]);
}

// ---------------------------------------------------------------------------
extern "C" void kernel_launch(void* const* d_in, const int* in_sizes, int n_in,
                              void* d_out, int out_size) {
    const float* x = (const float*)d_in[0];
    const int* mask = (const int*)d_in[1];
    float* out = (float*)d_out;

    reduce_kernel<<<NBLK, 1024>>>(x);
    combine_kernel<<<256, 256>>>();
    final_kernel<<<Bn, 1024>>>(mask, out);
}

// round 6
// speedup vs baseline: 1.1304x; 1.1304x over previous
#include <cuda_runtime.h>
#include <math.h>

// Problem shape (fixed): x [T=4, B=32, C=256, H=32, W=32]
#define Tn 4
#define Bn 32
#define Cn 256
#define Pn 1024
#define NSL 1024            // slices = B * 32 pixel-groups (32 pixels each, all channels)
#define NBLK 148            // persistent grid = one CTA per SM

// Final per-pixel sums: [sel][b][p], sel 0 = csum, 1 = ssq. 256 KB, L2-resident.
__device__ float g_comb[2 * Bn * Pn];

__device__ __forceinline__ float4 f4add(float4 a, float4 b) {
    return make_float4(a.x + b.x, a.y + b.y, a.z + b.z, a.w + b.w);
}

// ---------------------------------------------------------------------------
// Persistent reduce. Slice = (b, pg): 32 pixels (8 float4) x all 256 channels
// x 4 timesteps. 1024 threads: warp w covers channels [8w, 8w+8);
// lane l: f4 = l&7 (pixel quad), cpair = l>>3 -> channels c0 = 8w+2*cpair, c0+1.
// Per slice per thread: 8 x LDG.128. T-mean -> cs/sq, then channel reduction:
// shuffle over cpair (x4), smem over warps (x32), 16 threads write final
// per-pixel cs/sq to g_comb. Next slice's loads issued before the reduction.
// ---------------------------------------------------------------------------
__global__ void __launch_bounds__(1024, 1) reduce_kernel(const float* __restrict__ xf) {
    const float4* __restrict__ X = (const float4*)xf;
    const int tid   = threadIdx.x;
    const int w     = tid >> 5;
    const int l     = tid & 31;
    const int f4    = l & 7;
    const int cbase = w * 8 + (l >> 3) * 2;

    __shared__ float4 scs[32][8];
    __shared__ float4 ssq[32][8];

    const size_t tstr = (size_t)Bn * Cn * 256;   // t-plane stride in float4

    int sl = blockIdx.x;
    float4 r[8];

    {
        const int b = sl >> 5, pg = sl & 31;
        const size_t base = ((size_t)b * Cn + cbase) * 256 + pg * 8 + f4;
#pragma unroll
        for (int t = 0; t < 4; ++t) {
            r[t]     = __ldg(X + base + (size_t)t * tstr);
            r[4 + t] = __ldg(X + base + 256 + (size_t)t * tstr);
        }
    }

    for (;;) {
        // T-mean for both channels, then cs / ssq contribution
        float4 m0, m1;
        m0.x = (r[0].x + r[1].x + r[2].x + r[3].x) * 0.25f;
        m0.y = (r[0].y + r[1].y + r[2].y + r[3].y) * 0.25f;
        m0.z = (r[0].z + r[1].z + r[2].z + r[3].z) * 0.25f;
        m0.w = (r[0].w + r[1].w + r[2].w + r[3].w) * 0.25f;
        m1.x = (r[4].x + r[5].x + r[6].x + r[7].x) * 0.25f;
        m1.y = (r[4].y + r[5].y + r[6].y + r[7].y) * 0.25f;
        m1.z = (r[4].z + r[5].z + r[6].z + r[7].z) * 0.25f;
        m1.w = (r[4].w + r[5].w + r[6].w + r[7].w) * 0.25f;

        float4 cs4, sq4;
        cs4.x = m0.x + m1.x;  cs4.y = m0.y + m1.y;
        cs4.z = m0.z + m1.z;  cs4.w = m0.w + m1.w;
        sq4.x = fmaf(m0.x, m0.x, m1.x * m1.x);
        sq4.y = fmaf(m0.y, m0.y, m1.y * m1.y);
        sq4.z = fmaf(m0.z, m0.z, m1.z * m1.z);
        sq4.w = fmaf(m0.w, m0.w, m1.w * m1.w);

        const int cur  = sl;
        const int nxt  = sl + NBLK;
        const bool more = (nxt < NSL);

        if (more) {   // issue next slice's loads NOW; they fly across the reduction
            const int b = nxt >> 5, pg = nxt & 31;
            const size_t base = ((size_t)b * Cn + cbase) * 256 + pg * 8 + f4;
#pragma unroll
            for (int t = 0; t < 4; ++t) {
                r[t]     = __ldg(X + base + (size_t)t * tstr);
                r[4 + t] = __ldg(X + base + 256 + (size_t)t * tstr);
            }
        }

        // reduce over the 4 cpair-threads sharing this f4 within the warp
#pragma unroll
        for (int off = 8; off <= 16; off <<= 1) {
            cs4.x += __shfl_xor_sync(0xFFFFFFFFu, cs4.x, off);
            cs4.y += __shfl_xor_sync(0xFFFFFFFFu, cs4.y, off);
            cs4.z += __shfl_xor_sync(0xFFFFFFFFu, cs4.z, off);
            cs4.w += __shfl_xor_sync(0xFFFFFFFFu, cs4.w, off);
            sq4.x += __shfl_xor_sync(0xFFFFFFFFu, sq4.x, off);
            sq4.y += __shfl_xor_sync(0xFFFFFFFFu, sq4.y, off);
            sq4.z += __shfl_xor_sync(0xFFFFFFFFu, sq4.z, off);
            sq4.w += __shfl_xor_sync(0xFFFFFFFFu, sq4.w, off);
        }
        if (l < 8) { scs[w][l] = cs4; ssq[w][l] = sq4; }
        __syncthreads();

        if (tid < 16) {                       // sum the 32 warp partials
            const int sel = tid >> 3, ff = tid & 7;
            float4 acc = make_float4(0.f, 0.f, 0.f, 0.f);
#pragma unroll
            for (int ww = 0; ww < 32; ++ww)
                acc = f4add(acc, sel ? ssq[ww][ff] : scs[ww][ff]);
            const int b = cur >> 5, pg = cur & 31;
            float4* gc4 = (float4*)g_comb;
            gc4[(size_t)sel * (Bn * Pn / 4) + b * 256 + pg * 8 + ff] = acc;
        }

        if (!more) break;
        __syncthreads();      // protect smem reuse next iteration
        sl = nxt;
    }
}

// ---------------------------------------------------------------------------
// Final: per batch — per-pixel cs/sq (256 KB in L2), 3x3 zero-padded box
// filter, cosine collapse, mask, softmax over 1024 pixels.
// ---------------------------------------------------------------------------
__global__ void __launch_bounds__(1024) final_kernel(const int* __restrict__ mask,
                                                     float* __restrict__ out) {
    const int b    = blockIdx.x;
    const int tid  = threadIdx.x;           // pixel index
    const int h    = tid >> 5;
    const int w    = tid & 31;
    const int lane = tid & 31;
    const int wid  = tid >> 5;

    const float cs = __ldg(&g_comb[(size_t)b * Pn + tid]);
    const float sq = __ldg(&g_comb[(size_t)(Bn + b) * Pn + tid]);
    const int mraw = __ldg(&mask[(size_t)b * Pn + tid]);

    // 3x3 zero-padded box sum over 32x32
    __shared__ float s_cs[34 * 34];
    for (int i = tid; i < 34 * 34; i += 1024) s_cs[i] = 0.f;
    __syncthreads();
    s_cs[(h + 1) * 34 + (w + 1)] = cs;
    __syncthreads();

    float box = 0.f;
#pragma unroll
    for (int dh = 0; dh < 3; ++dh)
#pragma unroll
        for (int dw = 0; dw < 3; ++dw)
            box += s_cs[(h + dh) * 34 + (w + dw)];

    const float lm  = box * (1.f / 9.f);
    const float nx  = sqrtf(sq);
    const float ny  = 16.f * fabsf(lm);       // sqrt(C)=16
    const float sim = (lm * cs) / (fmaxf(nx, 1e-6f) * fmaxf(ny, 1e-6f));
    const float score = mraw ? -INFINITY : -sim;

    // block softmax over 1024 entries
    __shared__ float red[32];
    __shared__ float bc[2];

    float m = score;
#pragma unroll
    for (int o = 16; o; o >>= 1) m = fmaxf(m, __shfl_xor_sync(0xFFFFFFFFu, m, o));
    if (lane == 0) red[wid] = m;
    __syncthreads();
    if (wid == 0) {
        float v = red[lane];
#pragma unroll
        for (int o = 16; o; o >>= 1) v = fmaxf(v, __shfl_xor_sync(0xFFFFFFFFu, v, o));
        if (lane == 0) bc[0] = v;
    }
    __syncthreads();
    const float gmax = bc[0];

    const float e = __expf(score - gmax);
    float s = e;
#pragma unroll
    for (int o = 16; o; o >>= 1) s += __shfl_xor_sync(0xFFFFFFFFu, s, o);
    if (lane == 0) red[wid] = s;
    __syncthreads();
    if (wid == 0) {
        float v = red[lane];
#pragma unroll
        for (int o = 16; o; o >>= 1) v += __shfl_xor_sync(0xFFFFFFFFu, v, o);
        if (lane == 0) bc[1] = v;
    }
    __syncthreads();

    out[(size_t)b * Pn + tid] = e * __frcp_rn(bc[1]);
}

// ---------------------------------------------------------------------------
extern "C" void kernel_launch(void* const* d_in, const int* in_sizes, int n_in,
                              void* d_out, int out_size) {
    const float* x = (const float*)d_in[0];
    const int* mask = (const int*)d_in[1];
    float* out = (float*)d_out;

    reduce_kernel<<<NBLK, 1024>>>(x);
    final_kernel<<<Bn, 1024>>>(mask, out);
}